// round 3
// baseline (speedup 1.0000x reference)
#include <cuda_runtime.h>

// ---------------------------------------------------------------------------
// SSIM 3D, separable 11-tap Gaussian (sigma=1.5), VALID padding.
// Round 3: register-ring column walks (H then D), fused W-conv + SSIM pass.
// Conv coefficients are device constexpr -> fold to FFMA immediates (rt 1).
// ---------------------------------------------------------------------------

__device__ constexpr float CG[11] = {
    0.0010283817f, 0.0075987700f, 0.0360007700f, 0.1093607000f,
    0.2130055500f, 0.2660117200f,
    0.2130055500f, 0.1093607000f, 0.0360007700f, 0.0075987700f,
    0.0010283817f
};

// s1: [f][n][oh(182)][d(192)][w(192)]   (after H conv)
// s2: [f][n][od(182)][oh(182)][w(192)]  (after H+D conv)
static const size_t FS1 = (size_t)2 * 182 * 192 * 192;   // 13,418,496
static const size_t FS2 = (size_t)2 * 182 * 182 * 192;   // 12,719,616
__device__ float d_s1[5 * FS1];
__device__ float d_s2[5 * FS2];

__device__ unsigned d_minbits;
__device__ unsigned d_maxbits;
__device__ float    d_c1c2[2];
__device__ float    d_bsum[8372];

// ---------------------------------------------------------------------------

__global__ void init_kernel() {
    d_minbits = 0xFFFFFFFFu;
    d_maxbits = 0u;
}

__device__ __forceinline__ float mono2f(unsigned u) {
    return (u & 0x80000000u) ? __uint_as_float(u ^ 0x80000000u)
                             : __uint_as_float(~u);
}

__global__ void const_kernel() {
    float mx = mono2f(d_maxbits);
    float mn = mono2f(d_minbits);
    float max_val = (mx > 128.0f) ? 255.0f : 1.0f;
    float min_val = (mn < -0.5f) ? -1.0f : 0.0f;
    float L = max_val - min_val;
    float c1 = 0.01f * L, c2 = 0.03f * L;
    d_c1c2[0] = c1 * c1;
    d_c1c2[1] = c2 * c2;
}

// ---------------------------------------------------------------------------
// Pass A: H conv fused with the 5 pointwise products + img1 min/max.
// Thread = (n, d, w), walks h 0..191 with a 5x11 register ring.
// 73728 threads = 288 blocks x 256. Fully coalesced loads and stores.
// ---------------------------------------------------------------------------

#define PASSA_STEP(J, H)                                                     \
    {                                                                        \
        float x = __ldg(&img1[ib + (size_t)(H) * 192]);                      \
        float y = __ldg(&img2[ib + (size_t)(H) * 192]);                      \
        unsigned ux = __float_as_uint(x);                                    \
        ux = (ux & 0x80000000u) ? ~ux : (ux | 0x80000000u);                  \
        lmin = min(lmin, ux);                                                \
        lmax = max(lmax, ux);                                                \
        float v[5];                                                          \
        v[0] = x; v[1] = y; v[2] = x * x; v[3] = y * y; v[4] = x * y;        \
        _Pragma("unroll")                                                    \
        for (int f = 0; f < 5; f++) {                                        \
            acc[f][(J)] = CG[0] * v[f];                                      \
            _Pragma("unroll")                                                \
            for (int k = 1; k < 11; k++)                                     \
                acc[f][((J) + 11 - k) % 11] += CG[k] * v[f];                 \
        }                                                                    \
        if ((H) >= 10) {                                                     \
            size_t o = ob + (size_t)((H) - 10) * 36864;                      \
            const int e = ((J) + 1) % 11;                                    \
            d_s1[o]             = acc[0][e];                                 \
            d_s1[FS1 + o]       = acc[1][e];                                 \
            d_s1[2 * FS1 + o]   = acc[2][e];                                 \
            d_s1[3 * FS1 + o]   = acc[3][e];                                 \
            d_s1[4 * FS1 + o]   = acc[4][e];                                 \
        }                                                                    \
    }

__global__ void __launch_bounds__(256) passA_kernel(
    const float* __restrict__ img1, const float* __restrict__ img2) {
    int tid = blockIdx.x * 256 + threadIdx.x;
    int w  = tid % 192;
    int nd = tid / 192;                 // n*192 + d
    int n  = nd / 192;
    int d  = nd % 192;

    const size_t ib = (size_t)nd * 36864 + (size_t)w;                    // + h*192
    const size_t ob = (size_t)n * 182 * 36864 + (size_t)d * 192 + (size_t)w; // + od*36864

    float acc[5][11];
    unsigned lmin = 0xFFFFFFFFu, lmax = 0u;

    #pragma unroll 1
    for (int hb = 0; hb < 187; hb += 11) {
        #pragma unroll
        for (int j = 0; j < 11; j++) {
            PASSA_STEP(j, hb + j)
        }
    }
    // tail: h = 187..191 (187 % 11 == 0, so slot index = j)
    #pragma unroll
    for (int j = 0; j < 5; j++) {
        PASSA_STEP(j, 187 + j)
    }

    // block min/max reduction -> atomics
    #pragma unroll
    for (int off = 16; off; off >>= 1) {
        lmin = min(lmin, __shfl_down_sync(0xFFFFFFFFu, lmin, off));
        lmax = max(lmax, __shfl_down_sync(0xFFFFFFFFu, lmax, off));
    }
    __shared__ unsigned smin[8], smax[8];
    int wid = threadIdx.x >> 5, lane = threadIdx.x & 31;
    if (lane == 0) { smin[wid] = lmin; smax[wid] = lmax; }
    __syncthreads();
    if (threadIdx.x < 8) {
        lmin = smin[threadIdx.x];
        lmax = smax[threadIdx.x];
        #pragma unroll
        for (int off = 4; off; off >>= 1) {
            lmin = min(lmin, __shfl_down_sync(0xFFu, lmin, off));
            lmax = max(lmax, __shfl_down_sync(0xFFu, lmax, off));
        }
        if (threadIdx.x == 0) {
            atomicMin(&d_minbits, lmin);
            atomicMax(&d_maxbits, lmax);
        }
    }
}

// ---------------------------------------------------------------------------
// Pass B: D conv. Thread = (n, oh, w), walks d 0..191 with a 5x11 ring.
// 69888 threads = 273 blocks x 256. 5 independent loads per step (MLP=5).
// ---------------------------------------------------------------------------

#define PASSB_STEP(J, D)                                                     \
    {                                                                        \
        size_t iaddr = ib + (size_t)(D) * 192;                               \
        float v[5];                                                          \
        v[0] = __ldg(&d_s1[iaddr]);                                          \
        v[1] = __ldg(&d_s1[FS1 + iaddr]);                                    \
        v[2] = __ldg(&d_s1[2 * FS1 + iaddr]);                                \
        v[3] = __ldg(&d_s1[3 * FS1 + iaddr]);                                \
        v[4] = __ldg(&d_s1[4 * FS1 + iaddr]);                                \
        _Pragma("unroll")                                                    \
        for (int f = 0; f < 5; f++) {                                        \
            acc[f][(J)] = CG[0] * v[f];                                      \
            _Pragma("unroll")                                                \
            for (int k = 1; k < 11; k++)                                     \
                acc[f][((J) + 11 - k) % 11] += CG[k] * v[f];                 \
        }                                                                    \
        if ((D) >= 10) {                                                     \
            size_t o = ob + (size_t)((D) - 10) * 34944;                      \
            const int e = ((J) + 1) % 11;                                    \
            d_s2[o]             = acc[0][e];                                 \
            d_s2[FS2 + o]       = acc[1][e];                                 \
            d_s2[2 * FS2 + o]   = acc[2][e];                                 \
            d_s2[3 * FS2 + o]   = acc[3][e];                                 \
            d_s2[4 * FS2 + o]   = acc[4][e];                                 \
        }                                                                    \
    }

__global__ void __launch_bounds__(256) passB_kernel() {
    int tid = blockIdx.x * 256 + threadIdx.x;
    int w    = tid % 192;
    int rest = tid / 192;               // n*182 + oh
    int oh   = rest % 182;
    int n    = rest / 182;

    const size_t ib = (size_t)rest * 36864 + (size_t)w;                  // + d*192
    const size_t ob = (size_t)n * 182 * 34944 + (size_t)oh * 192 + (size_t)w; // + od*34944

    float acc[5][11];

    #pragma unroll 1
    for (int db = 0; db < 187; db += 11) {
        #pragma unroll
        for (int j = 0; j < 11; j++) {
            PASSB_STEP(j, db + j)
        }
    }
    #pragma unroll
    for (int j = 0; j < 5; j++) {
        PASSB_STEP(j, 187 + j)
    }
}

// ---------------------------------------------------------------------------
// Pass C: W conv + SSIM + block-sum. Block = (n, od, tile of 8 oh rows).
// Loads 5 fields x nrows x 192 into smem (float4), then 208 worker threads
// each produce a strip of 7 outputs for one (row, strip) across all 5 fields.
// ---------------------------------------------------------------------------
__global__ void __launch_bounds__(256) passC_kernel() {
    __shared__ float sm[5][8][192];
    __shared__ float sred[256];

    int bid  = blockIdx.x;
    int t    = bid % 23;
    int rest = bid / 23;
    int od   = rest % 182;
    int n    = rest / 182;
    int oh0  = t * 8;
    int nrows = (oh0 + 8 <= 182) ? 8 : (182 - oh0);

    size_t base = ((size_t)(n * 182 + od) * 182 + oh0) * 192;
    int total4 = 5 * nrows * 48;
    for (int i = threadIdx.x; i < total4; i += 256) {
        int c4 = i % 48;
        int rr = (i / 48) % nrows;
        int f  = i / (48 * nrows);
        float4 v = *(const float4*)(&d_s2[(size_t)f * FS2 + base + (size_t)rr * 192 + c4 * 4]);
        *(float4*)(&sm[f][rr][c4 * 4]) = v;
    }
    __syncthreads();

    const float C1 = d_c1c2[0];
    const float C2 = d_c1c2[1];
    float lsum = 0.f;

    int u = threadIdx.x;
    int s = u % 26;          // strip 0..25 (7 outputs each: 26*7 = 182)
    int r = u / 26;          // row
    if (r < nrows && u < 208) {
        int w0 = s * 7;
        float res[5][7];
        #pragma unroll
        for (int f = 0; f < 5; f++) {
            float win[17];
            #pragma unroll
            for (int i = 0; i < 17; i++) win[i] = sm[f][r][w0 + i];
            #pragma unroll
            for (int o = 0; o < 7; o++) {
                float a = CG[0] * win[o];
                #pragma unroll
                for (int k = 1; k < 11; k++) a += CG[k] * win[o + k];
                res[f][o] = a;
            }
        }
        #pragma unroll
        for (int o = 0; o < 7; o++) {
            float mu1 = res[0][o], mu2 = res[1][o];
            float m11 = mu1 * mu1, m22 = mu2 * mu2, m12 = mu1 * mu2;
            float s11 = res[2][o] - m11;
            float s22 = res[3][o] - m22;
            float s12 = res[4][o] - m12;
            float v1 = 2.f * s12 + C2;
            float v2 = s11 + s22 + C2;
            float num = (2.f * m12 + C1) * v1;
            float den = (m11 + m22 + C1) * v2;
            lsum += __fdividef(num, den);
        }
    }

    sred[threadIdx.x] = lsum;
    __syncthreads();
    #pragma unroll
    for (int off = 128; off; off >>= 1) {
        if (threadIdx.x < off) sred[threadIdx.x] += sred[threadIdx.x + off];
        __syncthreads();
    }
    if (threadIdx.x == 0) d_bsum[blockIdx.x] = sred[0];
}

// Deterministic final reduction over 8372 block sums.
__global__ void final_kernel(float* __restrict__ out) {
    __shared__ double sd[256];
    double s = 0.0;
    for (int i = threadIdx.x; i < 8372; i += 256) s += (double)d_bsum[i];
    sd[threadIdx.x] = s;
    __syncthreads();
    #pragma unroll
    for (int off = 128; off; off >>= 1) {
        if (threadIdx.x < off) sd[threadIdx.x] += sd[threadIdx.x + off];
        __syncthreads();
    }
    if (threadIdx.x == 0)
        out[0] = (float)(sd[0] / 12057136.0);   // 2 * 182^3
}

// ---------------------------------------------------------------------------

extern "C" void kernel_launch(void* const* d_in, const int* in_sizes, int n_in,
                              void* d_out, int out_size) {
    const float* img1 = (const float*)d_in[0];
    const float* img2 = (const float*)d_in[1];
    float* out = (float*)d_out;

    init_kernel<<<1, 1>>>();
    passA_kernel<<<288, 256>>>(img1, img2);     // 2*192*192 columns, walk h
    const_kernel<<<1, 1>>>();
    passB_kernel<<<273, 256>>>();               // 2*182*192 columns, walk d
    passC_kernel<<<8372, 256>>>();              // (n, od, oh-tile): W conv + SSIM
    final_kernel<<<1, 256>>>(out);
}

// round 4
// speedup vs baseline: 1.1617x; 1.1617x over previous
#include <cuda_runtime.h>

// ---------------------------------------------------------------------------
// SSIM 3D, separable 11-tap Gaussian, VALID. Round 4:
// smem-tiled stencils for H and D axes; DRAM accesses are bulk coalesced fills.
// ---------------------------------------------------------------------------

__device__ constexpr float CG[11] = {
    0.0010283817f, 0.0075987700f, 0.0360007700f, 0.1093607000f,
    0.2130055500f, 0.2660117200f,
    0.2130055500f, 0.1093607000f, 0.0360007700f, 0.0075987700f,
    0.0010283817f
};

// s1: [f][n][d][h][w(192 stride, 182 valid, pad cols stay 0)]
// s2: [f][n][oh(182)][d(192)][w(192 stride)]
static const size_t FS1 = (size_t)2 * 192 * 192 * 192;   // 14,155,776
static const size_t FS2 = (size_t)2 * 182 * 192 * 192;   // 13,418,496
__device__ float d_s1[5 * FS1];
__device__ float d_s2[5 * FS2];

__device__ unsigned d_minbits;
__device__ unsigned d_maxbits;
__device__ float    d_c1c2[2];
__device__ float    d_bsum[4368];

// ---------------------------------------------------------------------------

__global__ void init_kernel() {
    d_minbits = 0xFFFFFFFFu;
    d_maxbits = 0u;
}

__device__ __forceinline__ float mono2f(unsigned u) {
    return (u & 0x80000000u) ? __uint_as_float(u ^ 0x80000000u)
                             : __uint_as_float(~u);
}
__device__ __forceinline__ void mono_acc(float f, unsigned& mn, unsigned& mx) {
    unsigned u = __float_as_uint(f);
    u = (u & 0x80000000u) ? ~u : (u | 0x80000000u);
    mn = min(mn, u);
    mx = max(mx, u);
}

__global__ void const_kernel() {
    float mx = mono2f(d_maxbits);
    float mn = mono2f(d_minbits);
    float max_val = (mx > 128.0f) ? 255.0f : 1.0f;
    float min_val = (mn < -0.5f) ? -1.0f : 0.0f;
    float L = max_val - min_val;
    float c1 = 0.01f * L, c2 = 0.03f * L;
    d_c1c2[0] = c1 * c1;
    d_c1c2[1] = c2 * c2;
}

// ---------------------------------------------------------------------------
// Pass 1: W conv + 5 products + img1 min/max. Block = (n,d, 8 h-rows).
// 192 threads; float4 tile fill (4 independent f4/thread) then 8-row compute.
// ---------------------------------------------------------------------------
__global__ void __launch_bounds__(192) pass1_kernel(
    const float* __restrict__ img1, const float* __restrict__ img2) {
    __shared__ float sx[8 * 192];
    __shared__ float sy[8 * 192];

    int hg = blockIdx.x % 24;
    int nd = blockIdx.x / 24;          // n*192 + d
    int h0 = hg * 8;
    size_t base = ((size_t)nd * 192 + h0) * 192;
    int tid = threadIdx.x;

    unsigned lmin = 0xFFFFFFFFu, lmax = 0u;
    const float4* p1 = (const float4*)(img1 + base);
    const float4* p2 = (const float4*)(img2 + base);
    #pragma unroll
    for (int j = 0; j < 2; j++) {
        int idx = tid + j * 192;       // 0..383 float4
        float4 a = __ldg(&p1[idx]);
        float4 b = __ldg(&p2[idx]);
        ((float4*)sx)[idx] = a;
        ((float4*)sy)[idx] = b;
        mono_acc(a.x, lmin, lmax); mono_acc(a.y, lmin, lmax);
        mono_acc(a.z, lmin, lmax); mono_acc(a.w, lmin, lmax);
    }
    __syncthreads();

    if (tid < 182) {
        size_t ob = base + tid;        // s1 per-field offset == input offset (same dims)
        #pragma unroll
        for (int r = 0; r < 8; r++) {
            float a0 = 0.f, a1 = 0.f, a2 = 0.f, a3 = 0.f, a4 = 0.f;
            #pragma unroll
            for (int k = 0; k < 11; k++) {
                float g = CG[k];
                float x = sx[r * 192 + tid + k];
                float y = sy[r * 192 + tid + k];
                float tx = g * x, ty = g * y;
                a0 += tx;
                a1 += ty;
                a2 += tx * x;
                a3 += ty * y;
                a4 += tx * y;
            }
            size_t o = ob + (size_t)r * 192;
            d_s1[o]           = a0;
            d_s1[FS1 + o]     = a1;
            d_s1[2 * FS1 + o] = a2;
            d_s1[3 * FS1 + o] = a3;
            d_s1[4 * FS1 + o] = a4;
        }
    }

    // min/max block reduce -> atomics
    #pragma unroll
    for (int off = 16; off; off >>= 1) {
        lmin = min(lmin, __shfl_down_sync(0xFFFFFFFFu, lmin, off));
        lmax = max(lmax, __shfl_down_sync(0xFFFFFFFFu, lmax, off));
    }
    __shared__ unsigned smin[6], smax[6];
    int wid = tid >> 5, lane = tid & 31;
    if (lane == 0) { smin[wid] = lmin; smax[wid] = lmax; }
    __syncthreads();
    if (tid == 0) {
        #pragma unroll
        for (int i = 1; i < 6; i++) {
            lmin = min(lmin, smin[i]);
            lmax = max(lmax, smax[i]);
        }
        lmin = min(lmin, smin[0]); lmax = max(lmax, smax[0]);
        atomicMin(&d_minbits, lmin);
        atomicMax(&d_maxbits, lmax);
    }
}

// ---------------------------------------------------------------------------
// Pass 2: H conv. Block = ((f,n,d) plane, w-tile of 64). smem 192x64 (49KB).
// Fill with float4, then 14 strips x 13 outputs x 64 w via 11-slot ring.
// ---------------------------------------------------------------------------
__global__ void __launch_bounds__(256) pass2_kernel() {
    __shared__ float sm[192 * 64];

    int wt    = blockIdx.x % 3;
    int plane = blockIdx.x / 3;        // (f*2+n)*192 + d
    int d  = plane % 192;
    int fn = plane / 192;
    int f = fn >> 1, n = fn & 1;
    size_t splane = (size_t)fn % 2 == 0 ? 0 : 0;  // (unused, silence nothing)
    size_t sbase = (size_t)f * FS1 + ((size_t)(fn & 1) * 192 + d) * (size_t)(192 * 192);

    // fill: 192 rows x 16 float4
    for (int i = threadIdx.x; i < 192 * 16; i += 256) {
        int h = i >> 4, c = i & 15;
        float4 v = __ldg((const float4*)(d_s1 + sbase + (size_t)h * 192 + wt * 64) + c);
        ((float4*)sm)[h * 16 + c] = v;
    }
    __syncthreads();

    size_t obase = (size_t)f * FS2 + (size_t)n * 182 * (192 * 192)
                 + (size_t)d * 192 + (size_t)wt * 64;

    for (int i = threadIdx.x; i < 896; i += 256) {   // 64 w x 14 strips
        int w = i & 63;
        int s = i >> 6;
        int h0 = s * 13;
        float acc[11];
        #pragma unroll
        for (int j = 0; j < 23; j++) {
            float v = sm[(h0 + j) * 64 + w];
            const int J = j % 11;
            acc[J] = CG[0] * v;
            #pragma unroll
            for (int k = 1; k < 11; k++)
                acc[(J + 11 - k) % 11] += CG[k] * v;
            if (j >= 10) {
                int oh = h0 + j - 10;
                d_s2[obase + (size_t)oh * (192 * 192) + w] = acc[(J + 1) % 11];
            }
        }
    }
}

// ---------------------------------------------------------------------------
// Pass 3: D conv (5 fields) + SSIM + block sum. Block = (n, oh, w-tile 16).
// smem 5x192x16 (61KB). 14 strips x 13 outputs, 5x11 ring, SSIM inline.
// ---------------------------------------------------------------------------
__global__ void __launch_bounds__(256) pass3_kernel() {
    __shared__ float sm[5][192 * 16];
    __shared__ float sred[256];

    int wt   = blockIdx.x % 12;
    int rest = blockIdx.x / 12;
    int oh = rest % 182;
    int n  = rest / 182;

    size_t pb = ((size_t)(n * 182 + oh)) * (192 * 192) + (size_t)wt * 16;

    for (int i = threadIdx.x; i < 5 * 192 * 4; i += 256) {   // 3840 float4
        int c = i & 3;
        int dd = (i >> 2) % 192;
        int f  = i / 768;
        float4 v = __ldg((const float4*)(d_s2 + (size_t)f * FS2 + pb + (size_t)dd * 192) + c);
        ((float4*)(&sm[f][0]))[dd * 4 + c] = v;
    }
    __syncthreads();

    const float C1 = d_c1c2[0];
    const float C2 = d_c1c2[1];
    float lsum = 0.f;
    int tid = threadIdx.x;

    if (tid < 224) {
        int w = tid & 15;
        int s = tid >> 4;              // strip 0..13
        int ow = wt * 16 + w;
        if (ow < 182) {
            int d0 = s * 13;
            float acc[5][11];
            #pragma unroll
            for (int j = 0; j < 23; j++) {
                const int J = j % 11;
                float v0 = sm[0][(d0 + j) * 16 + w];
                float v1 = sm[1][(d0 + j) * 16 + w];
                float v2 = sm[2][(d0 + j) * 16 + w];
                float v3 = sm[3][(d0 + j) * 16 + w];
                float v4 = sm[4][(d0 + j) * 16 + w];
                acc[0][J] = CG[0] * v0;
                acc[1][J] = CG[0] * v1;
                acc[2][J] = CG[0] * v2;
                acc[3][J] = CG[0] * v3;
                acc[4][J] = CG[0] * v4;
                #pragma unroll
                for (int k = 1; k < 11; k++) {
                    const int e = (J + 11 - k) % 11;
                    acc[0][e] += CG[k] * v0;
                    acc[1][e] += CG[k] * v1;
                    acc[2][e] += CG[k] * v2;
                    acc[3][e] += CG[k] * v3;
                    acc[4][e] += CG[k] * v4;
                }
                if (j >= 10) {
                    const int e = (J + 1) % 11;
                    float mu1 = acc[0][e], mu2 = acc[1][e];
                    float m11 = mu1 * mu1, m22 = mu2 * mu2, m12 = mu1 * mu2;
                    float s11 = acc[2][e] - m11;
                    float s22 = acc[3][e] - m22;
                    float s12 = acc[4][e] - m12;
                    float va = 2.f * s12 + C2;
                    float vb = s11 + s22 + C2;
                    float num = (2.f * m12 + C1) * va;
                    float den = (m11 + m22 + C1) * vb;
                    lsum += __fdividef(num, den);
                }
            }
        }
    }

    sred[tid] = lsum;
    __syncthreads();
    #pragma unroll
    for (int off = 128; off; off >>= 1) {
        if (tid < off) sred[tid] += sred[tid + off];
        __syncthreads();
    }
    if (tid == 0) d_bsum[blockIdx.x] = sred[0];
}

// Deterministic final reduction over 4368 block sums.
__global__ void final_kernel(float* __restrict__ out) {
    __shared__ double sd[256];
    double s = 0.0;
    for (int i = threadIdx.x; i < 4368; i += 256) s += (double)d_bsum[i];
    sd[threadIdx.x] = s;
    __syncthreads();
    #pragma unroll
    for (int off = 128; off; off >>= 1) {
        if (threadIdx.x < off) sd[threadIdx.x] += sd[threadIdx.x + off];
        __syncthreads();
    }
    if (threadIdx.x == 0)
        out[0] = (float)(sd[0] / 12057136.0);   // 2 * 182^3
}

// ---------------------------------------------------------------------------

extern "C" void kernel_launch(void* const* d_in, const int* in_sizes, int n_in,
                              void* d_out, int out_size) {
    const float* img1 = (const float*)d_in[0];
    const float* img2 = (const float*)d_in[1];
    float* out = (float*)d_out;

    init_kernel<<<1, 1>>>();
    pass1_kernel<<<9216, 192>>>(img1, img2);   // 2*192*192 rows / 8
    const_kernel<<<1, 1>>>();
    pass2_kernel<<<5760, 256>>>();             // 5*2*192 planes x 3 w-tiles
    pass3_kernel<<<4368, 256>>>();             // 2*182 x 12 w-tiles
    final_kernel<<<1, 256>>>(out);
}